// round 12
// baseline (speedup 1.0000x reference)
#include <cuda_runtime.h>
#include <math_constants.h>

#define B_    4
#define C_    256
#define H_    64
#define W_    64
#define NROI  128
#define PLANE 4096            // 64*64 floats, row stride 64

// Block = (b, channel-pair): stage both planes; warp-task = (roi, ch-pair).
// Per stripe i: Phase A = warp-uniform column maxima (lanes = aligned float2
// over roi x-extent, conflict-free), Phase B = 14 lanes finalize (ch, j) bins
// into a smem staging buffer; one coalesced 98-float store per task.
// Bin bounds: exact integer math, bit-identical to reference f32 bounds
// (rel_err == 0, rounds 4-11). Deterministic ballot compaction.
__global__ __launch_bounds__(256) void roi_pool_sep2(
    const float* __restrict__ feat,
    const int*   __restrict__ rois,
    float*       __restrict__ out)
{
    __shared__ __align__(16) float plane[2 * PLANE];   // 32 KB
    __shared__ __align__(16) float cmax[8][2][52];     // 3.3 KB colmax scratch
    __shared__ __align__(16) float obuf[8][100];       // 3.2 KB output staging
    __shared__ int s_idx[NROI], s_x1[NROI], s_y1[NROI], s_nl[NROI];
    __shared__ unsigned char s_hb[NROI][8], s_wb[NROI][8];
    __shared__ int s_wcnt[4];

    const int tid  = threadIdx.x;
    const int lane = tid & 31;
    const int wid  = tid >> 5;
    const int blk  = blockIdx.x;          // b*128 + cpair
    const int b    = blk >> 7;
    const int c0   = (blk & 127) << 1;

    // ---- phase 0: deterministic compaction (order = original roi index) ----
    bool match = false;
    if (tid < NROI)
        match = (__ldg(rois + tid * 5) == b);
    const unsigned mball = __ballot_sync(0xffffffffu, match);
    if (lane == 0 && wid < 4) s_wcnt[wid] = __popc(mball);
    __syncthreads();
    const int cnt = s_wcnt[0] + s_wcnt[1] + s_wcnt[2] + s_wcnt[3];

    if (match) {
        int p = __popc(mball & ((1u << lane) - 1u));
        for (int w = 0; w < wid; ++w) p += s_wcnt[w];
        const int x1 = __ldg(rois + tid * 5 + 1);
        const int y1 = __ldg(rois + tid * 5 + 2);
        const int x2 = __ldg(rois + tid * 5 + 3);
        const int y2 = __ldg(rois + tid * 5 + 4);
        const int rh = y2 - y1 + 1;       // 5..48
        const int rw = x2 - x1 + 1;       // 5..48
        s_idx[p] = tid;
        s_x1[p]  = x1;
        s_y1[p]  = y1;
        s_nl[p]  = ((x2 >> 1) - (x1 >> 1)) + 1;   // float2 lanes needed, <=25
        #pragma unroll
        for (int i = 0; i < 8; ++i) {
            s_hb[p][i] = (unsigned char)((i * rh) / 7);
            s_wb[p][i] = (unsigned char)((i * rw) / 7);
        }
    }

    // ---- phase 1: stage the two planes (2048 float4, 8 per thread) ----
    {
        const float4* src = (const float4*)(feat + ((size_t)b * C_ + c0) * PLANE);
        float4* dst = (float4*)plane;
        #pragma unroll
        for (int kk = 0; kk < 8; ++kk)
            dst[kk * 256 + tid] = __ldg(src + kk * 256 + tid);
    }
    __syncthreads();

    // ---- phase 2: warp-tasks k = wid, wid+8, ... ----
    for (int k = wid; k < cnt; k += 8) {
        const int x1 = s_x1[k], y1 = s_y1[k], nl = s_nl[k];
        const int xb = x1 & ~1;           // even-aligned start column
        const int ox = x1 & 1;            // roi col rx -> cmax index rx+ox
        const float* p0 = plane + y1 * W_ + xb + 2 * lane;

        #pragma unroll 1
        for (int i = 0; i < 7; ++i) {
            const int hs = s_hb[k][i], he = s_hb[k][i + 1];

            // -- Phase A: column maxima for stripe i (warp-uniform bounds) --
            if (lane < nl && he > hs) {
                float2 a = make_float2(-CUDART_INF_F, -CUDART_INF_F);
                float2 c = a;
                const float* q = p0 + hs * W_;
                for (int y = hs; y < he; ++y) {
                    const float2 v0 = *(const float2*)q;
                    const float2 v1 = *(const float2*)(q + PLANE);
                    a.x = fmaxf(a.x, v0.x);  a.y = fmaxf(a.y, v0.y);
                    c.x = fmaxf(c.x, v1.x);  c.y = fmaxf(c.y, v1.y);
                    q += W_;
                }
                *(float2*)&cmax[wid][0][2 * lane] = a;
                *(float2*)&cmax[wid][1][2 * lane] = c;
            }
            __syncwarp();

            // -- Phase B: lanes 0..13 finalize (ch, j) bins of stripe i --
            if (lane < 14) {
                const int ch = (lane >= 7);
                const int j  = lane - ch * 7;
                const int ws = s_wb[k][j], we = s_wb[k][j + 1];
                const bool valid = (he > hs) && (we > ws);

                float m = -CUDART_INF_F;
                const float* cm = &cmax[wid][ch][ox];
                for (int rx = ws; rx < we; ++rx)
                    m = fmaxf(m, cm[rx]);

                obuf[wid][ch * 49 + i * 7 + j] = valid ? m : 0.0f;
            }
            __syncwarp();
        }

        // -- flush: 98 contiguous floats (bins of c0 then c0+1) --
        const size_t ob = ((size_t)s_idx[k] * C_ + c0) * 49;
        for (int u = lane; u < 98; u += 32)
            out[ob + u] = obuf[wid][u];
        __syncwarp();
    }
}

extern "C" void kernel_launch(void* const* d_in, const int* in_sizes, int n_in,
                              void* d_out, int out_size) {
    const float* features = (const float*)d_in[0];
    const int*   rois     = (const int*)d_in[1];
    float*       out      = (float*)d_out;

    roi_pool_sep2<<<B_ * (C_ / 2), 256>>>(features, rois, out);
}

// round 13
// speedup vs baseline: 1.6042x; 1.6042x over previous
#include <cuda_runtime.h>
#include <math_constants.h>

#define B_    4
#define C_    256
#define H_    64
#define W_    64
#define NROI  128
#define CPB   4                 // channels per block
#define THREADS 256

// Dynamic smem layout (69 KB):
//   [0, 65536)            float4 plane4[4096]   — [y*64+x] -> 4 channels
//   [65536, +512)         int    s_idx[128]
//   [66048, +512)         int    s_x1[128]
//   [66560, +512)         int    s_y1[128]
//   [67072, +1024)        uchar  s_hb[128][8]
//   [68096, +1024)        uchar  s_wb[128][8]
//   [69120, +16)          int    s_wcnt[4]
#define SMEM_BYTES 69152

__device__ __forceinline__ float4 fmax4(float4 a, float4 b) {
    return make_float4(fmaxf(a.x, b.x), fmaxf(a.y, b.y),
                       fmaxf(a.z, b.z), fmaxf(a.w, b.w));
}

// Block = (b, 4-channel group, roi-parity). Stage 4 planes channel-interleaved;
// thread-per-bin tasks read 4 channels per LDS.128.
// Bin bounds: exact integer math, bit-identical to reference f32 bounds
// (rel_err == 0, rounds 4-12). Deterministic ballot compaction (R10).
__global__ __launch_bounds__(THREADS) void roi_pool_c4(
    const float* __restrict__ feat,
    const int*   __restrict__ rois,
    float*       __restrict__ out)
{
    extern __shared__ __align__(16) char smem[];
    float4*        plane4 = (float4*)smem;
    int*           s_idx  = (int*)(smem + 65536);
    int*           s_x1   = (int*)(smem + 66048);
    int*           s_y1   = (int*)(smem + 66560);
    unsigned char (*s_hb)[8] = (unsigned char(*)[8])(smem + 67072);
    unsigned char (*s_wb)[8] = (unsigned char(*)[8])(smem + 68096);
    int*           s_wcnt = (int*)(smem + 69120);

    const int tid  = threadIdx.x;
    const int lane = tid & 31;
    const int wid  = tid >> 5;
    const int blk  = blockIdx.x;            // ((b*64 + grp) << 1) | half
    const int half = blk & 1;
    const int bcp  = blk >> 1;
    const int b    = bcp >> 6;
    const int c0   = (bcp & 63) << 2;       // channels c0 .. c0+3

    // ---- phase 0: deterministic compaction (order = original roi index) ----
    bool match = false;
    if (tid < NROI)
        match = (__ldg(rois + tid * 5) == b);
    const unsigned mball = __ballot_sync(0xffffffffu, match);
    if (lane == 0 && wid < 4) s_wcnt[wid] = __popc(mball);
    __syncthreads();
    const int cnt = s_wcnt[0] + s_wcnt[1] + s_wcnt[2] + s_wcnt[3];

    if (match) {
        int p = __popc(mball & ((1u << lane) - 1u));
        for (int w = 0; w < wid; ++w) p += s_wcnt[w];
        const int x1 = __ldg(rois + tid * 5 + 1);
        const int y1 = __ldg(rois + tid * 5 + 2);
        const int x2 = __ldg(rois + tid * 5 + 3);
        const int y2 = __ldg(rois + tid * 5 + 4);
        const int rh = y2 - y1 + 1;          // 5..48
        const int rw = x2 - x1 + 1;          // 5..48
        s_idx[p] = tid;
        s_x1[p]  = x1;
        s_y1[p]  = y1;
        #pragma unroll
        for (int i = 0; i < 8; ++i) {
            s_hb[p][i] = (unsigned char)((i * rh) / 7);
            s_wb[p][i] = (unsigned char)((i * rw) / 7);
        }
    }

    // ---- phase 1: stage 4 planes channel-interleaved ----
    // px g: read feat[(b*256 + c0+cc)*4096 + g] for cc=0..3 (each coalesced),
    // write one conflict-free STS.128.
    {
        const float* f0 = feat + ((size_t)b * C_ + c0) * (H_ * W_);
        #pragma unroll
        for (int kk = 0; kk < 16; ++kk) {
            const int g = kk * THREADS + tid;
            float4 v;
            v.x = __ldg(f0 + g);
            v.y = __ldg(f0 + 4096 + g);
            v.z = __ldg(f0 + 8192 + g);
            v.w = __ldg(f0 + 12288 + g);
            plane4[g] = v;
        }
    }
    __syncthreads();

    // ---- phase 2: thread-per-bin tasks over my roi half, 4 channels each ----
    const int nmine = (cnt > half) ? ((cnt - half + 1) >> 1) : 0;
    const int total = nmine * 49;
    for (int u = tid; u < total; u += THREADS) {
        const int km  = u / 49;
        const int bin = u - km * 49;
        const int k   = half + (km << 1);
        const int i   = (bin * 9363) >> 16;     // bin / 7 for bin < 49
        const int j   = bin - i * 7;

        const int hs = s_hb[k][i], he = s_hb[k][i + 1];
        const int ws = s_wb[k][j], we = s_wb[k][j + 1];
        const int nx = we - ws;
        const bool valid = (he > hs) && (nx > 0);

        int idx = (s_y1[k] + hs) * W_ + s_x1[k] + ws;
        float4 m = make_float4(-CUDART_INF_F, -CUDART_INF_F,
                               -CUDART_INF_F, -CUDART_INF_F);
        for (int y = hs; y < he; ++y) {
            #pragma unroll 2
            for (int xx = 0; xx < nx; ++xx)
                m = fmax4(m, plane4[idx + xx]);
            idx += W_;
        }

        const size_t ob = ((size_t)s_idx[k] * C_ + c0) * 49 + bin;
        out[ob]           = valid ? m.x : 0.0f;
        out[ob + 49]      = valid ? m.y : 0.0f;
        out[ob + 2 * 49]  = valid ? m.z : 0.0f;
        out[ob + 3 * 49]  = valid ? m.w : 0.0f;
    }
}

extern "C" void kernel_launch(void* const* d_in, const int* in_sizes, int n_in,
                              void* d_out, int out_size) {
    const float* features = (const float*)d_in[0];
    const int*   rois     = (const int*)d_in[1];
    float*       out      = (float*)d_out;

    cudaFuncSetAttribute(roi_pool_c4,
                         cudaFuncAttributeMaxDynamicSharedMemorySize, SMEM_BYTES);

    // grid = 4 batches * 64 channel-groups * 2 roi-halves = 512 blocks
    roi_pool_c4<<<B_ * (C_ / CPB) * 2, THREADS, SMEM_BYTES>>>(features, rois, out);
}